// round 4
// baseline (speedup 1.0000x reference)
#include <cuda_runtime.h>
#include <cuda_bf16.h>

#define BB 32
#define QQ 900
#define CC 92
#define TI 12          // rows per block in cost kernel (900 % 12 == 0)
#define NJV 225        // 900 / 4 float4 columns
#define BIGV 100000000.0f

// scratch: -softmax(pred_logits)  [B,Q,C]  (10.6 MB, static device array — no alloc)
__device__ float g_negprob[BB * QQ * CC];

// ---------------------------------------------------------------------------
// Kernel A: negated softmax over C=92, one warp per (b,i) row.
// MUFU (EX2/RCP) load here is trivial (~1k cycles chip-wide).
// ---------------------------------------------------------------------------
__global__ __launch_bounds__(128) void softmax_neg_kernel(
    const float* __restrict__ logits)
{
    int warp = (blockIdx.x * blockDim.x + threadIdx.x) >> 5;
    int lane = threadIdx.x & 31;
    if (warp >= BB * QQ) return;

    const float* row = logits + (size_t)warp * CC;
    // lanes cover c = lane, lane+32, lane+64 (lane+64 valid iff lane < 28)
    float v0 = row[lane];
    float v1 = row[lane + 32];
    bool  has2 = (lane + 64) < CC;
    float v2 = has2 ? row[lane + 64] : -3.0e38f;

    float m = fmaxf(v0, fmaxf(v1, v2));
    #pragma unroll
    for (int s = 16; s > 0; s >>= 1)
        m = fmaxf(m, __shfl_xor_sync(0xffffffffu, m, s));

    float e0 = __expf(v0 - m);
    float e1 = __expf(v1 - m);
    float e2 = has2 ? __expf(v2 - m) : 0.0f;

    float s = e0 + e1 + e2;
    #pragma unroll
    for (int t = 16; t > 0; t >>= 1)
        s += __shfl_xor_sync(0xffffffffu, s, t);

    float rinv = __fdividef(1.0f, s);

    float* o = g_negprob + (size_t)warp * CC;
    o[lane]      = -e0 * rinv;
    o[lane + 32] = -e1 * rinv;
    if (has2) o[lane + 64] = -e2 * rinv;
}

// ---------------------------------------------------------------------------
// Kernel B: cost[b,i,j] = 0.25*L1(pred_i, box_j) - prob[i,lab_j] - GIoU(i,j),
//           masked to BIG where area_j <= 0.
// Block: (b, i-tile of TI rows) x all 900 j. Thread: 4 consecutive j (float4).
// Class-prob tile [TI,92] staged in smem; gathers via LDS.
// Enclosing box via identity ew = iw + jw - dx (no extra min/max).
// Divisions on the MUFU pipe (hidden under fma/alu issue).
// ---------------------------------------------------------------------------
__global__ __launch_bounds__(256) void cost_kernel(
    const float* __restrict__ pred_boxes,   // [B,Q,4] cxcywh
    const float* __restrict__ boxes,        // [B,Q,4] cxcywh
    const float* __restrict__ area,         // [B,Q]
    const int*   __restrict__ labels,       // [B,Q]
    float*       __restrict__ out)          // [B,Q,Q]
{
    const int b  = blockIdx.y;
    const int i0 = blockIdx.x * TI;

    // i-side row scalars: cx,cy,w,h, x0,y0,x1,y1, area1
    __shared__ float s_row[TI][9];
    // negated softmax probs for the TI rows of this block
    __shared__ float s_np[TI * CC];      // 1104 floats = 4416 B

    const int tid = threadIdx.x;
    if (tid < TI) {
        float4 pb = *(const float4*)(pred_boxes + ((size_t)(b * QQ + i0 + tid)) * 4);
        float x0 = pb.x - 0.5f * pb.z;
        float y0 = pb.y - 0.5f * pb.w;
        float x1 = pb.x + 0.5f * pb.z;
        float y1 = pb.y + 0.5f * pb.w;
        s_row[tid][0] = pb.x;  s_row[tid][1] = pb.y;
        s_row[tid][2] = pb.z;  s_row[tid][3] = pb.w;
        s_row[tid][4] = x0;    s_row[tid][5] = y0;
        s_row[tid][6] = x1;    s_row[tid][7] = y1;
        s_row[tid][8] = pb.z * pb.w;   // area1 = w*h
    }
    // cooperative load of the negprob tile (contiguous, coalesced)
    {
        const float* np_g = g_negprob + ((size_t)(b * QQ + i0)) * CC;
        #pragma unroll
        for (int t = tid; t < TI * CC; t += 256)
            s_np[t] = np_g[t];
    }
    __syncthreads();

    if (tid >= NJV) return;    // 225 active threads; sync already done

    const int j0 = tid * 4;

    // ---- j-side data for my 4 columns, held in registers ----
    float jcx[4], jcy[4], jw[4], jh[4];
    float jx0[4], jy0[4], jx1[4], jy1[4], ja2[4];
    int   lab[4];
    bool  ok[4];

    {
        const float4* bp = (const float4*)(boxes + ((size_t)(b * QQ + j0)) * 4);
        #pragma unroll
        for (int k = 0; k < 4; k++) {
            float4 v = bp[k];
            jcx[k] = v.x; jcy[k] = v.y; jw[k] = v.z; jh[k] = v.w;
            jx0[k] = v.x - 0.5f * v.z;
            jy0[k] = v.y - 0.5f * v.w;
            jx1[k] = v.x + 0.5f * v.z;
            jy1[k] = v.y + 0.5f * v.w;
            ja2[k] = v.z * v.w;
        }
        int4 lv = *(const int4*)(labels + b * QQ + j0);
        lab[0] = lv.x; lab[1] = lv.y; lab[2] = lv.z; lab[3] = lv.w;
        float4 av = *(const float4*)(area + b * QQ + j0);
        ok[0] = av.x > 0.0f; ok[1] = av.y > 0.0f;
        ok[2] = av.z > 0.0f; ok[3] = av.w > 0.0f;
    }

    float* orow = out + ((size_t)(b * QQ + i0)) * QQ + j0;

    #pragma unroll 1
    for (int r = 0; r < TI; r++) {
        const float icx = s_row[r][0], icy = s_row[r][1];
        const float iw_ = s_row[r][2], ih_ = s_row[r][3];
        const float ix0 = s_row[r][4], iy0 = s_row[r][5];
        const float ix1 = s_row[r][6], iy1 = s_row[r][7];
        const float ia1 = s_row[r][8];
        const float* np = s_np + r * CC;

        float res[4];
        #pragma unroll
        for (int k = 0; k < 4; k++) {
            // class cost (already negated prob) — LDS gather
            float cls = np[lab[k]];

            // bbox L1 (mean over 4 coords; abs folds into FADD src modifiers)
            float dcx = icx - jcx[k];
            float dcy = icy - jcy[k];
            float dw  = iw_ - jw[k];
            float dh  = ih_ - jh[k];
            float l1  = (fabsf(dcx) + fabsf(dcy)) + (fabsf(dw) + fabsf(dh));

            // intersection extents
            float ltx = fmaxf(ix0, jx0[k]);
            float lty = fmaxf(iy0, jy0[k]);
            float rbx = fminf(ix1, jx1[k]);
            float rby = fminf(iy1, jy1[k]);
            float dx  = rbx - ltx;
            float dy  = rby - lty;
            float inter = fmaxf(dx, 0.0f) * fmaxf(dy, 0.0f);

            // enclosing box via identity: ew = iw + jw - dx, eh = ih + jh - dy
            float ew  = (iw_ + jw[k]) - dx;
            float eh  = (ih_ + jh[k]) - dy;
            float enc = ew * eh;

            float uni = (ia1 + ja2[k]) - inter;

            float iou  = __fdividef(inter, uni);
            float tail = __fdividef(enc - uni, enc);
            // cost = 0.25*l1 + cls + tail - iou
            float c = fmaf(l1, 0.25f, cls) + (tail - iou);
            res[k] = ok[k] ? c : BIGV;
        }

        *(float4*)orow = make_float4(res[0], res[1], res[2], res[3]);
        orow += QQ;
    }
}

// ---------------------------------------------------------------------------
extern "C" void kernel_launch(void* const* d_in, const int* in_sizes, int n_in,
                              void* d_out, int out_size)
{
    const float* pred_logits = (const float*)d_in[0];
    const float* pred_boxes  = (const float*)d_in[1];
    const float* boxes       = (const float*)d_in[2];
    const float* area        = (const float*)d_in[3];
    const int*   labels      = (const int*)d_in[4];
    float* out = (float*)d_out;

    // Kernel A: 28800 rows, 1 warp each, 4 warps/block
    softmax_neg_kernel<<<(BB * QQ) / 4, 128>>>(pred_logits);

    // Kernel B: grid (i-tiles, batch)
    dim3 grid(QQ / TI, BB);
    cost_kernel<<<grid, 256>>>(pred_boxes, boxes, area, labels, out);
}

// round 6
// speedup vs baseline: 1.1263x; 1.1263x over previous
#include <cuda_runtime.h>
#include <cuda_bf16.h>

#define BB 32
#define QQ 900
#define CC 92
#define TI 12            // i-rows per block (900 % 12 == 0)
#define NP_PITCH 93      // 92 classes + BIG sentinel at col 92
#define BIGV 100000000.0f

__device__ __forceinline__ float rcpa(float x) {
    float r; asm("rcp.approx.f32 %0, %1;" : "=f"(r) : "f"(x)); return r;
}

// cost for one (i,j) pair; cls already = 1 - prob (or BIG if masked)
__device__ __forceinline__ float cost_one(
    float icx, float icy, float iw, float ih,
    float ix0, float iy0, float ix1, float iy1, float ia1,
    float jcx, float jcy, float jw, float jh,
    float jx0, float jy0, float jx1, float jy1, float ja2,
    float cls)
{
    float dcx = icx - jcx, dcy = icy - jcy;
    float dw  = iw  - jw,  dh  = ih  - jh;
    float l1  = (fabsf(dcx) + fabsf(dcy)) + (fabsf(dw) + fabsf(dh));

    float ltx = fmaxf(ix0, jx0), lty = fmaxf(iy0, jy0);
    float rbx = fminf(ix1, jx1), rby = fminf(iy1, jy1);
    float dx  = rbx - ltx,       dy  = rby - lty;
    float dxc = fmaxf(dx, 0.0f), dyc = fmaxf(dy, 0.0f);
    float inter = dxc * dyc;

    // enclosing box via identity: ew = iw + jw - dx (max-min = w1+w2-overlap)
    float ew  = (iw + jw) - dx;
    float eh  = (ih + jh) - dy;
    float enc = ew * eh;

    float uni = fmaf(dxc, -dyc, ia1 + ja2);     // union = a1+a2-inter

    // cost = 0.25*l1 + (1-prob) - uni/enc - inter/uni
    float t1 = fmaf(l1, 0.25f, cls);
    float t2 = fmaf(uni, -rcpa(enc), t1);
    return fmaf(inter, -rcpa(uni), t2);
}

__global__ __launch_bounds__(256, 4) void fused_cost_kernel(
    const float* __restrict__ pred_logits,  // [B,Q,C]
    const float* __restrict__ pred_boxes,   // [B,Q,4] cxcywh
    const float* __restrict__ boxes,        // [B,Q,4] cxcywh
    const float* __restrict__ area,         // [B,Q]
    const int*   __restrict__ labels,       // [B,Q]
    float*       __restrict__ out)          // [B,Q,Q]
{
    const int b   = blockIdx.y;
    const int i0  = blockIdx.x * TI;
    const int tid = threadIdx.x;
    const int wid = tid >> 5;
    const int lane = tid & 31;

    // i-side row scalars, 48B rows for LDS.128:
    //   [0]={cx,cy,w,h} [1]={x0,y0,x1,y1} [2]={area1,-,-,-}
    __shared__ float4 s_row4[TI][3];
    // (1 - softmax prob) table per row + BIG sentinel at col 92
    __shared__ float  s_np[TI * NP_PITCH];

    // --- prologue 1: i-side scalars ------------------------------------
    if (tid < TI) {
        float4 pb = *(const float4*)(pred_boxes + ((size_t)(b * QQ + i0 + tid)) * 4);
        float x0 = pb.x - 0.5f * pb.z;
        float y0 = pb.y - 0.5f * pb.w;
        float x1 = pb.x + 0.5f * pb.z;
        float y1 = pb.y + 0.5f * pb.w;
        s_row4[tid][0] = pb;
        s_row4[tid][1] = make_float4(x0, y0, x1, y1);
        s_row4[tid][2] = make_float4(pb.z * pb.w, 0.0f, 0.0f, 0.0f);
    }
    // sentinel column: one store per row, by thread 0
    if (tid == 0) {
        #pragma unroll
        for (int row = 0; row < TI; row++)
            s_np[row * NP_PITCH + CC] = BIGV;
    }

    // --- prologue 2: fused softmax, one warp per row --------------------
    for (int row = wid; row < TI; row += 8) {
        const float* rp = pred_logits + ((size_t)(b * QQ + i0 + row)) * CC;
        float v0 = rp[lane];
        float v1 = rp[lane + 32];
        bool  has2 = lane < (CC - 64);            // lane < 28
        float v2 = has2 ? rp[lane + 64] : -3.0e38f;

        float m = fmaxf(v0, fmaxf(v1, v2));
        #pragma unroll
        for (int s = 16; s > 0; s >>= 1)
            m = fmaxf(m, __shfl_xor_sync(0xffffffffu, m, s));

        float e0 = __expf(v0 - m);
        float e1 = __expf(v1 - m);
        float e2 = has2 ? __expf(v2 - m) : 0.0f;

        float s = e0 + e1 + e2;
        #pragma unroll
        for (int t = 16; t > 0; t >>= 1)
            s += __shfl_xor_sync(0xffffffffu, s, t);

        float rinv = rcpa(s);
        float* o = s_np + row * NP_PITCH;
        o[lane]      = fmaf(-e0, rinv, 1.0f);     // 1 - prob
        o[lane + 32] = fmaf(-e1, rinv, 1.0f);
        if (has2) o[lane + 64] = fmaf(-e2, rinv, 1.0f);
    }
    __syncthreads();

    // --- main: warps 0-6 do 4 j each (j=4t), warp 7 lanes 0-3 do j=896+.
    if (tid < 224) {
        const int j0 = tid * 4;

        float jcx[4], jcy[4], jw[4], jh[4];
        float jx0[4], jy0[4], jx1[4], jy1[4], ja2[4];
        const float* npp[4];
        {
            const float4* bp = (const float4*)(boxes + ((size_t)(b * QQ + j0)) * 4);
            #pragma unroll
            for (int k = 0; k < 4; k++) {
                float4 v = bp[k];
                jcx[k] = v.x; jcy[k] = v.y; jw[k] = v.z; jh[k] = v.w;
                jx0[k] = v.x - 0.5f * v.z;
                jy0[k] = v.y - 0.5f * v.w;
                jx1[k] = v.x + 0.5f * v.z;
                jy1[k] = v.y + 0.5f * v.w;
                ja2[k] = v.z * v.w;
            }
            int4   lv = *(const int4*)(labels + b * QQ + j0);
            float4 av = *(const float4*)(area + b * QQ + j0);
            npp[0] = s_np + (av.x > 0.0f ? lv.x : CC);
            npp[1] = s_np + (av.y > 0.0f ? lv.y : CC);
            npp[2] = s_np + (av.z > 0.0f ? lv.z : CC);
            npp[3] = s_np + (av.w > 0.0f ? lv.w : CC);
        }

        float* orow = out + ((size_t)(b * QQ + i0)) * QQ + j0;

        #pragma unroll
        for (int r = 0; r < TI; r++) {
            float4 a = s_row4[r][0];
            float4 c = s_row4[r][1];
            float  ia1 = s_row4[r][2].x;

            float res[4];
            #pragma unroll
            for (int k = 0; k < 4; k++) {
                float cls = npp[k][r * NP_PITCH];
                res[k] = cost_one(a.x, a.y, a.z, a.w,
                                  c.x, c.y, c.z, c.w, ia1,
                                  jcx[k], jcy[k], jw[k], jh[k],
                                  jx0[k], jy0[k], jx1[k], jy1[k], ja2[k],
                                  cls);
            }
            *(float4*)(orow + (size_t)r * QQ) = make_float4(res[0], res[1], res[2], res[3]);
        }
    } else if (tid < 228) {
        const int j = 896 + (tid - 224);          // j in [896, 900)

        float4 v = *(const float4*)(boxes + ((size_t)(b * QQ + j)) * 4);
        float jcx = v.x, jcy = v.y, jw = v.z, jh = v.w;
        float jx0 = v.x - 0.5f * v.z;
        float jy0 = v.y - 0.5f * v.w;
        float jx1 = v.x + 0.5f * v.z;
        float jy1 = v.y + 0.5f * v.w;
        float ja2 = v.z * v.w;
        int   lv = labels[b * QQ + j];
        float av = area[b * QQ + j];
        const float* npp = s_np + (av > 0.0f ? lv : CC);

        float* ocol = out + ((size_t)(b * QQ + i0)) * QQ + j;

        #pragma unroll 1
        for (int r = 0; r < TI; r++) {
            float4 a = s_row4[r][0];
            float4 c = s_row4[r][1];
            float  ia1 = s_row4[r][2].x;
            float cls = npp[r * NP_PITCH];
            ocol[(size_t)r * QQ] = cost_one(a.x, a.y, a.z, a.w,
                                            c.x, c.y, c.z, c.w, ia1,
                                            jcx, jcy, jw, jh,
                                            jx0, jy0, jx1, jy1, ja2,
                                            cls);
        }
    }
}

// ---------------------------------------------------------------------------
extern "C" void kernel_launch(void* const* d_in, const int* in_sizes, int n_in,
                              void* d_out, int out_size)
{
    const float* pred_logits = (const float*)d_in[0];
    const float* pred_boxes  = (const float*)d_in[1];
    const float* boxes       = (const float*)d_in[2];
    const float* area        = (const float*)d_in[3];
    const int*   labels      = (const int*)d_in[4];
    float* out = (float*)d_out;

    dim3 grid(QQ / TI, BB);
    fused_cost_kernel<<<grid, 256>>>(pred_logits, pred_boxes, boxes, area,
                                     labels, out);
}